// round 1
// baseline (speedup 1.0000x reference)
#include <cuda_runtime.h>
#include <cstdint>

#define M_TOT 32768
#define N_TOT 1024
#define K_TOT 1024
#define BM 128
#define BN 128
#define BK 32
#define LDSS 36   // smem row stride in floats (padded, 16B-aligned)

// 4MB scratch for permuted W (module-global: allowed scratch path)
__device__ float g_Wp[N_TOT * K_TOT];

// ---------------------------------------------------------------------------
// Kernel 0: permute W columns.  Wp[n, k] = W[n, (k%4)*256 + k/4]
// (inverse mapping, source-coalesced: j = q*256+h  ->  k = h*4+q)
// ---------------------------------------------------------------------------
__global__ void permute_w_kernel(const float* __restrict__ W) {
    int idx = blockIdx.x * blockDim.x + threadIdx.x;     // 0 .. 1M-1
    int n = idx >> 10;
    int j = idx & 1023;
    int q = j >> 8;          // 0..3
    int h = j & 255;         // 0..255
    int k = (h << 2) | q;
    g_Wp[(n << 10) + k] = W[idx];
}

// ---------------------------------------------------------------------------
// tf32 helpers
// ---------------------------------------------------------------------------
__device__ __forceinline__ float to_tf32(float x) {
    uint32_t u;
    asm("cvt.rna.tf32.f32 %0, %1;" : "=r"(u) : "f"(x));
    return __uint_as_float(u);
}

__device__ __forceinline__ void mma_tf32(float c[4],
                                         const uint32_t a[4],
                                         const uint32_t b[2]) {
    asm volatile(
        "mma.sync.aligned.m16n8k8.row.col.f32.tf32.tf32.f32 "
        "{%0,%1,%2,%3}, {%4,%5,%6,%7}, {%8,%9}, {%0,%1,%2,%3};\n"
        : "+f"(c[0]), "+f"(c[1]), "+f"(c[2]), "+f"(c[3])
        : "r"(a[0]), "r"(a[1]), "r"(a[2]), "r"(a[3]),
          "r"(b[0]), "r"(b[1]));
}

// ---------------------------------------------------------------------------
// Kernel 1: fused  out = cos(x + theta) @ Wp^T + bias
//   block tile 128x128x32, 8 warps (4 along M x 2 along N), warp tile 32x64
//   double-buffered smem, tf32 mma.sync
// ---------------------------------------------------------------------------
__global__ void __launch_bounds__(256)
qmha_gemm_kernel(const float* __restrict__ X,
                 const float* __restrict__ theta,
                 const float* __restrict__ bias,
                 float* __restrict__ out) {
    extern __shared__ float sm[];
    float* As = sm;                       // [2][BM*LDSS]
    float* Bs = sm + 2 * BM * LDSS;       // [2][BN*LDSS]

    const int tid  = threadIdx.x;
    const int warp = tid >> 5;
    const int lane = tid & 31;
    const int g    = lane >> 2;           // group id 0..7
    const int t    = lane & 3;            // thread in group 0..3
    const int wm   = (warp & 3) * 32;     // warp M offset within block
    const int wn   = (warp >> 2) * 64;    // warp N offset within block

    // block swizzle: bn fastest -> same-M blocks co-resident -> x reused in L2
    const int bn = (blockIdx.x & 7)  * BN;
    const int bm = (blockIdx.x >> 3) * BM;

    // gmem tile-load mapping: each thread loads 4 float4 per tile per matrix
    const int c4 = tid & 7;               // float4 column within 32-wide K tile
    const int r0 = tid >> 3;              // base row (stride 32 over i)

    const float4* X4  = (const float4*)X;
    const float4* Wp4 = (const float4*)g_Wp;
    const float4* Th4 = (const float4*)theta;

    float4 aR[4], bR[4], thv;

    float acc[2][8][4];
#pragma unroll
    for (int i = 0; i < 2; i++)
#pragma unroll
        for (int j = 0; j < 8; j++)
#pragma unroll
            for (int v = 0; v < 4; v++) acc[i][j][v] = 0.f;

    auto LOAD = [&](int kt) {
        const int kq = kt * (BK / 4);     // float4 column offset
#pragma unroll
        for (int i = 0; i < 4; i++) {
            aR[i] = X4[(size_t)(bm + r0 + 32 * i) * (K_TOT / 4) + kq + c4];
            bR[i] = Wp4[(size_t)(bn + r0 + 32 * i) * (K_TOT / 4) + kq + c4];
        }
        thv = Th4[kq + c4];
    };

    auto STORE = [&](int buf) {
        float* a  = As + buf * BM * LDSS;
        float* bb = Bs + buf * BN * LDSS;
#pragma unroll
        for (int i = 0; i < 4; i++) {
            float4 v = aR[i];
            v.x = to_tf32(cosf(v.x + thv.x));
            v.y = to_tf32(cosf(v.y + thv.y));
            v.z = to_tf32(cosf(v.z + thv.z));
            v.w = to_tf32(cosf(v.w + thv.w));
            *(float4*)(a + (r0 + 32 * i) * LDSS + c4 * 4) = v;

            float4 w = bR[i];
            w.x = to_tf32(w.x);
            w.y = to_tf32(w.y);
            w.z = to_tf32(w.z);
            w.w = to_tf32(w.w);
            *(float4*)(bb + (r0 + 32 * i) * LDSS + c4 * 4) = w;
        }
    };

    auto COMPUTE = [&](int buf) {
        const float* a  = As + buf * BM * LDSS;
        const float* bb = Bs + buf * BN * LDSS;
#pragma unroll
        for (int ks = 0; ks < 4; ks++) {
            const int kc = ks * 8;
            uint32_t af[2][4];
            uint32_t bf[8][2];
#pragma unroll
            for (int i = 0; i < 2; i++) {
                const int mr = wm + i * 16 + g;
                af[i][0] = __float_as_uint(a[mr * LDSS + kc + t]);
                af[i][1] = __float_as_uint(a[(mr + 8) * LDSS + kc + t]);
                af[i][2] = __float_as_uint(a[mr * LDSS + kc + t + 4]);
                af[i][3] = __float_as_uint(a[(mr + 8) * LDSS + kc + t + 4]);
            }
#pragma unroll
            for (int j = 0; j < 8; j++) {
                const int nr = wn + j * 8 + g;
                bf[j][0] = __float_as_uint(bb[nr * LDSS + kc + t]);
                bf[j][1] = __float_as_uint(bb[nr * LDSS + kc + t + 4]);
            }
#pragma unroll
            for (int i = 0; i < 2; i++)
#pragma unroll
                for (int j = 0; j < 8; j++)
                    mma_tf32(acc[i][j], af[i], bf[j]);
        }
    };

    const int NKT = K_TOT / BK;           // 32
    LOAD(0);
    STORE(0);
    __syncthreads();

    for (int kt = 0; kt < NKT; kt++) {
        if (kt + 1 < NKT) LOAD(kt + 1);
        COMPUTE(kt & 1);
        if (kt + 1 < NKT) STORE((kt + 1) & 1);
        __syncthreads();
    }

    // epilogue: add bias, store fp32
#pragma unroll
    for (int i = 0; i < 2; i++) {
        const int mr = bm + wm + i * 16 + g;
#pragma unroll
        for (int j = 0; j < 8; j++) {
            const int nc = bn + wn + j * 8 + 2 * t;
            const float b0 = __ldg(bias + nc);
            const float b1 = __ldg(bias + nc + 1);
            *(float2*)(out + (size_t)mr * N_TOT + nc) =
                make_float2(acc[i][j][0] + b0, acc[i][j][1] + b1);
            *(float2*)(out + (size_t)(mr + 8) * N_TOT + nc) =
                make_float2(acc[i][j][2] + b0, acc[i][j][3] + b1);
        }
    }
}

// ---------------------------------------------------------------------------
// launch
// ---------------------------------------------------------------------------
extern "C" void kernel_launch(void* const* d_in, const int* in_sizes, int n_in,
                              void* d_out, int out_size) {
    const float* x     = (const float*)d_in[0];   // (32768, 1, 1024)
    const float* theta = (const float*)d_in[1];   // (256, 4) == flat k-order
    const float* W     = (const float*)d_in[2];   // (1024, 1024)
    const float* b     = (const float*)d_in[3];   // (1024,)
    float* out = (float*)d_out;

    // W permute: 1M elements / 256 = 4096 blocks
    permute_w_kernel<<<4096, 256>>>(W);

    const int smem_bytes = 2 * (BM + BN) * LDSS * sizeof(float); // 73728
    cudaFuncSetAttribute(qmha_gemm_kernel,
                         cudaFuncAttributeMaxDynamicSharedMemorySize,
                         smem_bytes);

    dim3 grid((M_TOT / BM) * (N_TOT / BN));       // 256 * 8 = 2048
    qmha_gemm_kernel<<<grid, 256, smem_bytes>>>(x, theta, b, out);
}

// round 3
// speedup vs baseline: 1.5613x; 1.5613x over previous
#include <cuda_runtime.h>
#include <cstdint>

#define M_TOT 32768
#define N_TOT 1024
#define K_TOT 1024
#define BM 128
#define BN 128
#define BK 32
#define STAGES 4
#define STAGE_BYTES (128 * 128)        // 16 KB per matrix per stage (128 rows x 128B)
#define NKT (K_TOT / BK)               // 32

// scratch: precomputed A = tf32(cos(x+theta)) [128MB] and permuted W [4MB]
__device__ float g_Axf[(size_t)M_TOT * K_TOT];
__device__ float g_Wp[N_TOT * K_TOT];

// ---------------------------------------------------------------------------
// Kernel 0: permute W columns + round to tf32.  Wp[n, h*4+q] = W[n, q*256+h]
// ---------------------------------------------------------------------------
__global__ void permute_w_kernel(const float* __restrict__ W) {
    int idx = blockIdx.x * blockDim.x + threadIdx.x;   // 0 .. 1M-1
    int n = idx >> 10;
    int j = idx & 1023;
    int q = j >> 8;
    int h = j & 255;
    int k = (h << 2) | q;
    uint32_t u;
    asm("cvt.rna.tf32.f32 %0, %1;" : "=r"(u) : "f"(W[idx]));
    g_Wp[(n << 10) + k] = __uint_as_float(u);
}

// ---------------------------------------------------------------------------
// Kernel 1: A = tf32(cos(x + theta)), elementwise, memory bound
// ---------------------------------------------------------------------------
__device__ __forceinline__ float cos_tf32(float x) {
    float c = cosf(x);
    uint32_t u;
    asm("cvt.rna.tf32.f32 %0, %1;" : "=r"(u) : "f"(c));
    return __uint_as_float(u);
}

__global__ void precompute_a_kernel(const float* __restrict__ X,
                                    const float* __restrict__ theta) {
    const size_t idx = (size_t)blockIdx.x * blockDim.x + threadIdx.x; // float4 id
    const float4* X4  = (const float4*)X;
    const float4* Th4 = (const float4*)theta;
    float4* A4 = (float4*)g_Axf;
    const int k4 = (int)(idx & (K_TOT / 4 - 1));
    const float4 th = __ldg(Th4 + k4);
    float4 v = __ldg(X4 + idx);
    v.x = cos_tf32(v.x + th.x);
    v.y = cos_tf32(v.y + th.y);
    v.z = cos_tf32(v.z + th.z);
    v.w = cos_tf32(v.w + th.w);
    A4[idx] = v;
}

// ---------------------------------------------------------------------------
// helpers
// ---------------------------------------------------------------------------
__device__ __forceinline__ uint32_t smem_u32(const void* p) {
    uint32_t a;
    asm("{ .reg .u64 t; cvta.to.shared.u64 t, %1; cvt.u32.u64 %0, t; }"
        : "=r"(a) : "l"(p));
    return a;
}

#define CP_ASYNC16(dst, src) \
    asm volatile("cp.async.cg.shared.global [%0], [%1], 16;" \
                 :: "r"(dst), "l"(src) : "memory")
#define CP_COMMIT() asm volatile("cp.async.commit_group;" ::: "memory")
#define CP_WAIT2()  asm volatile("cp.async.wait_group 2;" ::: "memory")

__device__ __forceinline__ void ldsm_x4(uint32_t* r, uint32_t addr) {
    asm volatile("ldmatrix.sync.aligned.m8n8.x4.shared.b16 {%0,%1,%2,%3}, [%4];"
                 : "=r"(r[0]), "=r"(r[1]), "=r"(r[2]), "=r"(r[3]) : "r"(addr));
}

__device__ __forceinline__ void mma_tf32(float* c, const uint32_t* a,
                                         const uint32_t* b) {
    asm volatile(
        "mma.sync.aligned.m16n8k8.row.col.f32.tf32.tf32.f32 "
        "{%0,%1,%2,%3}, {%4,%5,%6,%7}, {%8,%9}, {%0,%1,%2,%3};\n"
        : "+f"(c[0]), "+f"(c[1]), "+f"(c[2]), "+f"(c[3])
        : "r"(a[0]), "r"(a[1]), "r"(a[2]), "r"(a[3]), "r"(b[0]), "r"(b[1]));
}

// ---------------------------------------------------------------------------
// Kernel 2: out = Axf @ Wp^T + bias     (pure tf32 GEMM, mma.sync + ldmatrix)
//   block 128x128, BK=32, 8 warps (2M x 4N), warp tile 64x32
//   cp.async 4-stage pipeline, XOR-swizzled smem, ldmatrix.x4 fragments
// ---------------------------------------------------------------------------
__global__ void __launch_bounds__(256, 1)
qmha_gemm_kernel(const float* __restrict__ bias, float* __restrict__ out) {
    extern __shared__ char dsm[];
    const uint32_t base = (smem_u32(dsm) + 1023u) & ~1023u;
    const uint32_t smA = base;
    const uint32_t smB = base + STAGES * STAGE_BYTES;

    const int tid  = threadIdx.x;
    const int warp = tid >> 5;
    const int lane = tid & 31;
    const int g    = lane >> 2;
    const int t    = lane & 3;
    const int wm   = (warp & 1) * 64;     // warp M offset (2 warps along M)
    const int wn   = (warp >> 1) * 32;    // warp N offset (4 warps along N)

    // block swizzle: N fastest -> co-resident blocks share A tile in L2
    const int bn = (blockIdx.x & 7) * BN;
    const int bm = (blockIdx.x >> 3) * BM;

    // ---- producer (cp.async) per-thread mapping: 4 x 16B per matrix ----
    // e = tid + 256*j ; row = e>>3 ; cc = e&7 ; dst chunk = cc ^ (row&7)
    const float* aGm = g_Axf + (size_t)bm * K_TOT;
    const float* bGm = g_Wp + (size_t)bn * K_TOT;

    // ---- ldmatrix per-lane address components ----
    const int q = lane >> 3, i = lane & 7;
    const uint32_t aRowB = (uint32_t)(wm + ((q & 1) << 3) + i) * 128;
    const uint32_t aHi   = (uint32_t)(q >> 1);
    const uint32_t bRowB = (uint32_t)(wn + ((q >> 1) << 3) + i) * 128;
    const uint32_t bHi   = (uint32_t)(q & 1);

    float acc[4][4][4];
#pragma unroll
    for (int m = 0; m < 4; m++)
#pragma unroll
        for (int n = 0; n < 4; n++)
#pragma unroll
            for (int v = 0; v < 4; v++) acc[m][n][v] = 0.f;

    auto ISSUE = [&](int s, int kt) {
#pragma unroll
        for (int j = 0; j < 4; j++) {
            const int e = tid + 256 * j;
            const int row = e >> 3;
            const int cc = e & 7;
            const uint32_t doff = (uint32_t)row * 128
                                + (uint32_t)((cc ^ (row & 7)) << 4);
            const int soff = row * K_TOT + kt * BK + cc * 4;
            CP_ASYNC16(smA + s * STAGE_BYTES + doff, aGm + soff);
            CP_ASYNC16(smB + s * STAGE_BYTES + doff, bGm + soff);
        }
        CP_COMMIT();
    };

    // prologue: 3 stages in flight
    ISSUE(0, 0);
    ISSUE(1, 1);
    ISSUE(2, 2);

    for (int kt = 0; kt < NKT; kt++) {
        CP_WAIT2();
        __syncthreads();
        if (kt + 3 < NKT) ISSUE((kt + 3) & 3, kt + 3);
        else CP_COMMIT();

        const uint32_t aS = smA + (kt & 3) * STAGE_BYTES + aRowB;
        const uint32_t bS = smB + (kt & 3) * STAGE_BYTES + bRowB;
#pragma unroll
        for (int ks = 0; ks < 4; ks++) {
            const uint32_t ca = (uint32_t)((((2 * ks) | aHi) ^ i) << 4);
            const uint32_t cb = (uint32_t)((((2 * ks) | bHi) ^ i) << 4);
            uint32_t af[4][4], bf[2][4];
#pragma unroll
            for (int mt = 0; mt < 4; mt++)
                ldsm_x4(af[mt], aS + mt * 2048 + ca);
#pragma unroll
            for (int p = 0; p < 2; p++)
                ldsm_x4(bf[p], bS + p * 2048 + cb);
#pragma unroll
            for (int mt = 0; mt < 4; mt++)
#pragma unroll
                for (int nt = 0; nt < 4; nt++)
                    mma_tf32(acc[mt][nt], af[mt], &bf[nt >> 1][(nt & 1) * 2]);
        }
        __syncthreads();
    }

    // epilogue: + bias, fp32 out
#pragma unroll
    for (int mt = 0; mt < 4; mt++) {
        const int m = bm + wm + mt * 16 + g;
#pragma unroll
        for (int nt = 0; nt < 4; nt++) {
            const int n = bn + wn + nt * 8 + 2 * t;
            const float b0 = __ldg(bias + n);
            const float b1 = __ldg(bias + n + 1);
            *(float2*)(out + (size_t)m * N_TOT + n) =
                make_float2(acc[mt][nt][0] + b0, acc[mt][nt][1] + b1);
            *(float2*)(out + (size_t)(m + 8) * N_TOT + n) =
                make_float2(acc[mt][nt][2] + b0, acc[mt][nt][3] + b1);
        }
    }
}

// ---------------------------------------------------------------------------
// launch
// ---------------------------------------------------------------------------
extern "C" void kernel_launch(void* const* d_in, const int* in_sizes, int n_in,
                              void* d_out, int out_size) {
    const float* x     = (const float*)d_in[0];   // (32768, 1, 1024)
    const float* theta = (const float*)d_in[1];   // (256, 4)
    const float* W     = (const float*)d_in[2];   // (1024, 1024)
    const float* b     = (const float*)d_in[3];   // (1024,)
    float* out = (float*)d_out;

    permute_w_kernel<<<4096, 256>>>(W);
    precompute_a_kernel<<<(M_TOT * (K_TOT / 4)) / 256, 256>>>(x, theta);

    const int smem_bytes = 2 * STAGES * STAGE_BYTES + 1024;   // 132 KB
    cudaFuncSetAttribute(qmha_gemm_kernel,
                         cudaFuncAttributeMaxDynamicSharedMemorySize, smem_bytes);

    dim3 grid((M_TOT / BM) * (N_TOT / BN));       // 256 * 8 = 2048
    qmha_gemm_kernel<<<grid, 256, smem_bytes>>>(b, out);
}

// round 4
// speedup vs baseline: 2.7213x; 1.7429x over previous
#include <cuda_runtime.h>
#include <cuda_fp16.h>
#include <cstdint>

#define M_TOT 32768
#define N_TOT 1024
#define K_TOT 1024
#define BM 128
#define BN 128
#define BK 64
#define STAGES 4
#define STAGE_BYTES (128 * 128)        // 16 KB per matrix per stage (128 rows x 64 fp16)
#define NKT (K_TOT / BK)               // 16

// scratch: precomputed A = fp16(cos(x+theta)) [64MB] and permuted W fp16 [2MB]
__device__ __half g_Ah[(size_t)M_TOT * K_TOT];
__device__ __half g_Wph[N_TOT * K_TOT];

// ---------------------------------------------------------------------------
// Kernel 0: permute W columns + round to fp16.  Wph[n, h*4+q] = W[n, q*256+h]
// ---------------------------------------------------------------------------
__global__ void permute_w_kernel(const float* __restrict__ W) {
    int idx = blockIdx.x * blockDim.x + threadIdx.x;   // 0 .. 1M-1
    int n = idx >> 10;
    int j = idx & 1023;
    int q = j >> 8;
    int h = j & 255;
    int k = (h << 2) | q;
    g_Wph[(n << 10) + k] = __float2half_rn(W[idx]);
}

// ---------------------------------------------------------------------------
// Kernel 1: A = fp16(cos(x + theta)), elementwise, memory bound
// each thread: 8 elements (two float4 in, one 16B half8 out)
// ---------------------------------------------------------------------------
__global__ void precompute_a_kernel(const float* __restrict__ X,
                                    const float* __restrict__ theta) {
    const size_t idx = (size_t)blockIdx.x * blockDim.x + threadIdx.x; // half8 id
    const float4* X4  = (const float4*)X;
    const float4* Th4 = (const float4*)theta;
    const int k8 = (int)(idx & (K_TOT / 8 - 1));
    const float4 t0 = __ldg(Th4 + 2 * k8);
    const float4 t1 = __ldg(Th4 + 2 * k8 + 1);
    const float4 v0 = __ldg(X4 + 2 * idx);
    const float4 v1 = __ldg(X4 + 2 * idx + 1);
    __half h[8];
    h[0] = __float2half_rn(cosf(v0.x + t0.x));
    h[1] = __float2half_rn(cosf(v0.y + t0.y));
    h[2] = __float2half_rn(cosf(v0.z + t0.z));
    h[3] = __float2half_rn(cosf(v0.w + t0.w));
    h[4] = __float2half_rn(cosf(v1.x + t1.x));
    h[5] = __float2half_rn(cosf(v1.y + t1.y));
    h[6] = __float2half_rn(cosf(v1.z + t1.z));
    h[7] = __float2half_rn(cosf(v1.w + t1.w));
    ((uint4*)g_Ah)[idx] = *(const uint4*)h;
}

// ---------------------------------------------------------------------------
// helpers
// ---------------------------------------------------------------------------
__device__ __forceinline__ uint32_t smem_u32(const void* p) {
    uint32_t a;
    asm("{ .reg .u64 t; cvta.to.shared.u64 t, %1; cvt.u32.u64 %0, t; }"
        : "=r"(a) : "l"(p));
    return a;
}

#define CP_ASYNC16(dst, src) \
    asm volatile("cp.async.cg.shared.global [%0], [%1], 16;" \
                 :: "r"(dst), "l"(src) : "memory")
#define CP_COMMIT() asm volatile("cp.async.commit_group;" ::: "memory")
#define CP_WAIT2()  asm volatile("cp.async.wait_group 2;" ::: "memory")

__device__ __forceinline__ void ldsm_x4(uint32_t* r, uint32_t addr) {
    asm volatile("ldmatrix.sync.aligned.m8n8.x4.shared.b16 {%0,%1,%2,%3}, [%4];"
                 : "=r"(r[0]), "=r"(r[1]), "=r"(r[2]), "=r"(r[3]) : "r"(addr));
}

__device__ __forceinline__ void mma_f16(float* c, const uint32_t* a,
                                        const uint32_t* b) {
    asm volatile(
        "mma.sync.aligned.m16n8k16.row.col.f32.f16.f16.f32 "
        "{%0,%1,%2,%3}, {%4,%5,%6,%7}, {%8,%9}, {%0,%1,%2,%3};\n"
        : "+f"(c[0]), "+f"(c[1]), "+f"(c[2]), "+f"(c[3])
        : "r"(a[0]), "r"(a[1]), "r"(a[2]), "r"(a[3]), "r"(b[0]), "r"(b[1]));
}

// ---------------------------------------------------------------------------
// Kernel 2: out = Ah @ Wph^T + bias    (fp16 GEMM, mma.sync m16n8k16 + ldmatrix)
//   block 128x128, BK=64, 8 warps (2M x 4N), warp tile 64x32
//   cp.async 4-stage pipeline, XOR-swizzled smem (16B chunks)
// ---------------------------------------------------------------------------
__global__ void __launch_bounds__(256, 1)
qmha_gemm_kernel(const float* __restrict__ bias, float* __restrict__ out) {
    extern __shared__ char dsm[];
    const uint32_t base = (smem_u32(dsm) + 1023u) & ~1023u;
    const uint32_t smA = base;
    const uint32_t smB = base + STAGES * STAGE_BYTES;

    const int tid  = threadIdx.x;
    const int warp = tid >> 5;
    const int lane = tid & 31;
    const int g    = lane >> 2;
    const int t    = lane & 3;
    const int wm   = (warp & 1) * 64;     // warp M offset (2 warps along M)
    const int wn   = (warp >> 1) * 32;    // warp N offset (4 warps along N)

    // block swizzle: N fastest -> co-resident blocks share A tile in L2
    const int bn = (blockIdx.x & 7) * BN;
    const int bm = (blockIdx.x >> 3) * BM;

    const __half* aGm = g_Ah + (size_t)bm * K_TOT;
    const __half* bGm = g_Wph + (size_t)bn * K_TOT;

    // ---- ldmatrix per-lane address components ----
    // A: lanes 0-15 -> rows 0-15 (k lo 16B), lanes 16-31 -> rows 0-15 (k hi 16B)
    const int rA  = lane & 15;
    const int aHi = lane >> 4;
    const uint32_t aRowB = (uint32_t)(wm + rA) * 128;
    const uint32_t aSw   = (uint32_t)(rA & 7);
    // B: lanes 0-7 -> n0-7 kLo, 8-15 -> n0-7 kHi, 16-23 -> n8-15 kLo, 24-31 -> n8-15 kHi
    const int nLoc = (lane & 7) | ((lane >> 4) << 3);
    const int bHi  = (lane >> 3) & 1;
    const uint32_t bRowB = (uint32_t)(wn + nLoc) * 128;
    const uint32_t bSw   = (uint32_t)(nLoc & 7);

    float acc[4][4][4];
#pragma unroll
    for (int m = 0; m < 4; m++)
#pragma unroll
        for (int n = 0; n < 4; n++)
#pragma unroll
            for (int v = 0; v < 4; v++) acc[m][n][v] = 0.f;

    auto ISSUE = [&](int s, int kt) {
#pragma unroll
        for (int j = 0; j < 4; j++) {
            const int e = tid + 256 * j;
            const int row = e >> 3;                      // 0..127
            const int cc = e & 7;                        // 16B chunk in row
            const uint32_t doff = (uint32_t)row * 128
                                + (uint32_t)((cc ^ (row & 7)) << 4);
            const int soff = row * K_TOT + kt * BK + cc * 8;   // half elems
            CP_ASYNC16(smA + s * STAGE_BYTES + doff, aGm + soff);
            CP_ASYNC16(smB + s * STAGE_BYTES + doff, bGm + soff);
        }
        CP_COMMIT();
    };

    ISSUE(0, 0);
    ISSUE(1, 1);
    ISSUE(2, 2);

    for (int kt = 0; kt < NKT; kt++) {
        CP_WAIT2();
        __syncthreads();
        if (kt + 3 < NKT) ISSUE((kt + 3) & 3, kt + 3);
        else CP_COMMIT();

        const uint32_t aS = smA + (kt & 3) * STAGE_BYTES + aRowB;
        const uint32_t bS = smB + (kt & 3) * STAGE_BYTES + bRowB;
#pragma unroll
        for (int ks = 0; ks < 4; ks++) {               // 4 x k16 per BK=64
            const uint32_t ca = (uint32_t)((((2 * ks) | aHi) ^ aSw) << 4);
            const uint32_t cb = (uint32_t)((((2 * ks) | bHi) ^ bSw) << 4);
            uint32_t af[4][4], bf[2][4];
#pragma unroll
            for (int mt = 0; mt < 4; mt++)
                ldsm_x4(af[mt], aS + mt * 2048 + ca);   // 16 rows * 128B
#pragma unroll
            for (int p = 0; p < 2; p++)
                ldsm_x4(bf[p], bS + p * 2048 + cb);     // 16 n-rows * 128B
#pragma unroll
            for (int mt = 0; mt < 4; mt++)
#pragma unroll
                for (int nt = 0; nt < 4; nt++)
                    mma_f16(acc[mt][nt], af[mt], &bf[nt >> 1][(nt & 1) * 2]);
        }
        __syncthreads();
    }

    // epilogue: + bias, fp32 out
#pragma unroll
    for (int mt = 0; mt < 4; mt++) {
        const int m = bm + wm + mt * 16 + g;
#pragma unroll
        for (int nt = 0; nt < 4; nt++) {
            const int n = bn + wn + nt * 8 + 2 * t;
            const float b0 = __ldg(bias + n);
            const float b1 = __ldg(bias + n + 1);
            *(float2*)(out + (size_t)m * N_TOT + n) =
                make_float2(acc[mt][nt][0] + b0, acc[mt][nt][1] + b1);
            *(float2*)(out + (size_t)(m + 8) * N_TOT + n) =
                make_float2(acc[mt][nt][2] + b0, acc[mt][nt][3] + b1);
        }
    }
}

// ---------------------------------------------------------------------------
// launch
// ---------------------------------------------------------------------------
extern "C" void kernel_launch(void* const* d_in, const int* in_sizes, int n_in,
                              void* d_out, int out_size) {
    const float* x     = (const float*)d_in[0];   // (32768, 1, 1024)
    const float* theta = (const float*)d_in[1];   // (256, 4)
    const float* W     = (const float*)d_in[2];   // (1024, 1024)
    const float* b     = (const float*)d_in[3];   // (1024,)
    float* out = (float*)d_out;

    permute_w_kernel<<<4096, 256>>>(W);
    precompute_a_kernel<<<(M_TOT * (K_TOT / 8)) / 256, 256>>>(x, theta);

    const int smem_bytes = 2 * STAGES * STAGE_BYTES + 1024;   // 132 KB
    cudaFuncSetAttribute(qmha_gemm_kernel,
                         cudaFuncAttributeMaxDynamicSharedMemorySize, smem_bytes);

    dim3 grid((M_TOT / BM) * (N_TOT / BN));       // 256 * 8 = 2048
    qmha_gemm_kernel<<<grid, 256, smem_bytes>>>(b, out);
}

// round 5
// speedup vs baseline: 3.1889x; 1.1718x over previous
#include <cuda_runtime.h>
#include <cuda_fp16.h>
#include <cstdint>

#define M_TOT 32768
#define N_TOT 1024
#define K_TOT 1024
#define BM 128
#define BN 128
#define BK 64
#define STAGES 3
#define STAGE_BYTES (128 * 128)        // 16 KB per matrix per stage (128 rows x 64 fp16)
#define NKT (K_TOT / BK)               // 16
#define PRE_BLOCKS 16384               // precompute blocks (32768*128 half8 / 256)
#define PERM_BLOCKS 512                // permute blocks (1M elems / (256*8))

// scratch: precomputed A = fp16(cos(x+theta)) [64MB] and permuted W fp16 [2MB]
__device__ __half g_Ah[(size_t)M_TOT * K_TOT];
__device__ __half g_Wph[N_TOT * K_TOT];

// ---------------------------------------------------------------------------
// Kernel 0 (fused prep):
//  blocks [0, PRE_BLOCKS):               A = fp16(cos(x + theta))
//  blocks [PRE_BLOCKS, +PERM_BLOCKS):    Wph[n, h*4+q] = fp16(W[n, q*256+h])
// ---------------------------------------------------------------------------
__global__ void prep_kernel(const float* __restrict__ X,
                            const float* __restrict__ theta,
                            const float* __restrict__ W) {
    if (blockIdx.x < PRE_BLOCKS) {
        const size_t idx = (size_t)blockIdx.x * blockDim.x + threadIdx.x; // half8 id
        const float4* X4  = (const float4*)X;
        const float4* Th4 = (const float4*)theta;
        const int k8 = (int)(idx & (K_TOT / 8 - 1));
        const float4 t0 = __ldg(Th4 + 2 * k8);
        const float4 t1 = __ldg(Th4 + 2 * k8 + 1);
        const float4 v0 = __ldg(X4 + 2 * idx);
        const float4 v1 = __ldg(X4 + 2 * idx + 1);
        __half h[8];
        h[0] = __float2half_rn(cosf(v0.x + t0.x));
        h[1] = __float2half_rn(cosf(v0.y + t0.y));
        h[2] = __float2half_rn(cosf(v0.z + t0.z));
        h[3] = __float2half_rn(cosf(v0.w + t0.w));
        h[4] = __float2half_rn(cosf(v1.x + t1.x));
        h[5] = __float2half_rn(cosf(v1.y + t1.y));
        h[6] = __float2half_rn(cosf(v1.z + t1.z));
        h[7] = __float2half_rn(cosf(v1.w + t1.w));
        ((uint4*)g_Ah)[idx] = *(const uint4*)h;
    } else {
        // 8 elements per thread, source-coalesced
        const int base = ((int)blockIdx.x - PRE_BLOCKS) * (256 * 8)
                       + (int)threadIdx.x * 8;
#pragma unroll
        for (int e = 0; e < 8; e++) {
            const int idx = base + e;          // 0 .. 1M-1
            const int n = idx >> 10;
            const int j = idx & 1023;
            const int q = j >> 8;
            const int h = j & 255;
            const int k = (h << 2) | q;
            g_Wph[(n << 10) + k] = __float2half_rn(__ldg(W + idx));
        }
    }
}

// ---------------------------------------------------------------------------
// helpers
// ---------------------------------------------------------------------------
__device__ __forceinline__ uint32_t smem_u32(const void* p) {
    uint32_t a;
    asm("{ .reg .u64 t; cvta.to.shared.u64 t, %1; cvt.u32.u64 %0, t; }"
        : "=r"(a) : "l"(p));
    return a;
}

#define CP_ASYNC16(dst, src) \
    asm volatile("cp.async.cg.shared.global [%0], [%1], 16;" \
                 :: "r"(dst), "l"(src) : "memory")
#define CP_COMMIT() asm volatile("cp.async.commit_group;" ::: "memory")
#define CP_WAIT1()  asm volatile("cp.async.wait_group 1;" ::: "memory")

__device__ __forceinline__ void ldsm_x4(uint32_t* r, uint32_t addr) {
    asm volatile("ldmatrix.sync.aligned.m8n8.x4.shared.b16 {%0,%1,%2,%3}, [%4];"
                 : "=r"(r[0]), "=r"(r[1]), "=r"(r[2]), "=r"(r[3]) : "r"(addr));
}

__device__ __forceinline__ void mma_f16(float* c, const uint32_t* a,
                                        const uint32_t* b) {
    asm volatile(
        "mma.sync.aligned.m16n8k16.row.col.f32.f16.f16.f32 "
        "{%0,%1,%2,%3}, {%4,%5,%6,%7}, {%8,%9}, {%0,%1,%2,%3};\n"
        : "+f"(c[0]), "+f"(c[1]), "+f"(c[2]), "+f"(c[3])
        : "r"(a[0]), "r"(a[1]), "r"(a[2]), "r"(a[3]), "r"(b[0]), "r"(b[1]));
}

// ---------------------------------------------------------------------------
// Kernel 1: out = Ah @ Wph^T + bias    (fp16 GEMM, mma.sync m16n8k16 + ldmatrix)
//   block 128x128, BK=64, 8 warps (2M x 4N), warp tile 64x32
//   cp.async 3-stage pipeline, XOR-swizzled smem, ONE sync per iter, 2 CTA/SM
// ---------------------------------------------------------------------------
__global__ void __launch_bounds__(256, 2)
qmha_gemm_kernel(const float* __restrict__ bias, float* __restrict__ out) {
    extern __shared__ char dsm[];
    const uint32_t base = (smem_u32(dsm) + 1023u) & ~1023u;
    const uint32_t smA = base;
    const uint32_t smB = base + STAGES * STAGE_BYTES;

    const int tid  = threadIdx.x;
    const int warp = tid >> 5;
    const int lane = tid & 31;
    const int g    = lane >> 2;
    const int t    = lane & 3;
    const int wm   = (warp & 1) * 64;     // warp M offset (2 warps along M)
    const int wn   = (warp >> 1) * 32;    // warp N offset (4 warps along N)

    // block swizzle: N fastest -> co-resident blocks share A tile in L2
    const int bn = (blockIdx.x & 7) * BN;
    const int bm = (blockIdx.x >> 3) * BM;

    const __half* aGm = g_Ah + (size_t)bm * K_TOT;
    const __half* bGm = g_Wph + (size_t)bn * K_TOT;

    // ---- ldmatrix per-lane address components ----
    const int rA  = lane & 15;
    const int aHi = lane >> 4;
    const uint32_t aRowB = (uint32_t)(wm + rA) * 128;
    const uint32_t aSw   = (uint32_t)(rA & 7);
    const int nLoc = (lane & 7) | ((lane >> 4) << 3);
    const int bHi  = (lane >> 3) & 1;
    const uint32_t bRowB = (uint32_t)(wn + nLoc) * 128;
    const uint32_t bSw   = (uint32_t)(nLoc & 7);

    float acc[4][4][4];
#pragma unroll
    for (int m = 0; m < 4; m++)
#pragma unroll
        for (int n = 0; n < 4; n++)
#pragma unroll
            for (int v = 0; v < 4; v++) acc[m][n][v] = 0.f;

    auto ISSUE = [&](int s, int kt) {
#pragma unroll
        for (int j = 0; j < 4; j++) {
            const int e = tid + 256 * j;
            const int row = e >> 3;                      // 0..127
            const int cc = e & 7;                        // 16B chunk in row
            const uint32_t doff = (uint32_t)row * 128
                                + (uint32_t)((cc ^ (row & 7)) << 4);
            const int soff = row * K_TOT + kt * BK + cc * 8;   // half elems
            CP_ASYNC16(smA + s * STAGE_BYTES + doff, aGm + soff);
            CP_ASYNC16(smB + s * STAGE_BYTES + doff, bGm + soff);
        }
        CP_COMMIT();
    };

    ISSUE(0, 0);
    ISSUE(1, 1);

    int stage = 0;
    for (int kt = 0; kt < NKT; kt++) {
        CP_WAIT1();
        __syncthreads();                   // single barrier per iteration
        if (kt + 2 < NKT) {
            const int s = stage + 2 >= STAGES ? stage + 2 - STAGES : stage + 2;
            ISSUE(s, kt + 2);
        } else {
            CP_COMMIT();                   // keep wait_group counts aligned
        }

        const uint32_t aS = smA + stage * STAGE_BYTES + aRowB;
        const uint32_t bS = smB + stage * STAGE_BYTES + bRowB;
#pragma unroll
        for (int ks = 0; ks < 4; ks++) {               // 4 x k16 per BK=64
            const uint32_t ca = (uint32_t)((((2 * ks) | aHi) ^ aSw) << 4);
            const uint32_t cb = (uint32_t)((((2 * ks) | bHi) ^ bSw) << 4);
            uint32_t af[4][4], bf[2][4];
#pragma unroll
            for (int mt = 0; mt < 4; mt++)
                ldsm_x4(af[mt], aS + mt * 2048 + ca);   // 16 rows * 128B
#pragma unroll
            for (int p = 0; p < 2; p++)
                ldsm_x4(bf[p], bS + p * 2048 + cb);     // 16 n-rows * 128B
#pragma unroll
            for (int mt = 0; mt < 4; mt++)
#pragma unroll
                for (int nt = 0; nt < 4; nt++)
                    mma_f16(acc[mt][nt], af[mt], &bf[nt >> 1][(nt & 1) * 2]);
        }
        stage = stage + 1 >= STAGES ? 0 : stage + 1;
    }

    // epilogue: + bias, fp32 out
#pragma unroll
    for (int mt = 0; mt < 4; mt++) {
        const int m = bm + wm + mt * 16 + g;
#pragma unroll
        for (int nt = 0; nt < 4; nt++) {
            const int n = bn + wn + nt * 8 + 2 * t;
            const float b0 = __ldg(bias + n);
            const float b1 = __ldg(bias + n + 1);
            *(float2*)(out + (size_t)m * N_TOT + n) =
                make_float2(acc[mt][nt][0] + b0, acc[mt][nt][1] + b1);
            *(float2*)(out + (size_t)(m + 8) * N_TOT + n) =
                make_float2(acc[mt][nt][2] + b0, acc[mt][nt][3] + b1);
        }
    }
}

// ---------------------------------------------------------------------------
// launch
// ---------------------------------------------------------------------------
extern "C" void kernel_launch(void* const* d_in, const int* in_sizes, int n_in,
                              void* d_out, int out_size) {
    const float* x     = (const float*)d_in[0];   // (32768, 1, 1024)
    const float* theta = (const float*)d_in[1];   // (256, 4)
    const float* W     = (const float*)d_in[2];   // (1024, 1024)
    const float* b     = (const float*)d_in[3];   // (1024,)
    float* out = (float*)d_out;

    prep_kernel<<<PRE_BLOCKS + PERM_BLOCKS, 256>>>(x, theta, W);

    const int smem_bytes = 2 * STAGES * STAGE_BYTES + 1024;   // 97.25 KB
    cudaFuncSetAttribute(qmha_gemm_kernel,
                         cudaFuncAttributeMaxDynamicSharedMemorySize, smem_bytes);

    dim3 grid((M_TOT / BM) * (N_TOT / BN));       // 256 * 8 = 2048
    qmha_gemm_kernel<<<grid, 256, smem_bytes>>>(b, out);
}

// round 6
// speedup vs baseline: 3.4139x; 1.0705x over previous
#include <cuda_runtime.h>
#include <cuda_fp16.h>
#include <cstdint>

#define M_TOT 32768
#define N_TOT 1024
#define K_TOT 1024
#define BM 128
#define BN 128
#define BK 64
#define STAGES 3
#define TILE_BYTES 16384               // one 128x64 fp16 tile, swizzled
#define STAGE_BYTES (2 * TILE_BYTES)   // A tile + B tile
#define NKT (K_TOT / BK)               // 16
#define PRE_BLOCKS 16384               // A-precompute blocks
#define PERM_BLOCKS 512                // W-permute blocks

// scratch, both stored TILED + SWIZZLED:
//   g_Ah:  [bm_blk=256][kt=16][128x64 tile, 16KB, xor-swizzled]   (64 MB)
//   g_Wph: [bn_blk=8  ][kt=16][128x64 tile, 16KB, xor-swizzled]   ( 2 MB)
__device__ __half g_Ah[(size_t)M_TOT * K_TOT];
__device__ __half g_Wph[N_TOT * K_TOT];

// in-tile swizzled byte offset for (row 0..127, 16B-chunk cc 0..7)
__device__ __forceinline__ uint32_t tile_off(int row, int cc) {
    return (uint32_t)row * 128u + (uint32_t)((cc ^ (row & 7)) << 4);
}

// ---------------------------------------------------------------------------
// Kernel 0 (fused prep):
//  blocks [0, PRE_BLOCKS):            A = fp16(__cosf(x + theta)), tiled layout
//  blocks [PRE_BLOCKS, +PERM_BLOCKS): Wph[n, h*4+q] = fp16(W[n, q*256+h]), tiled
// ---------------------------------------------------------------------------
__global__ void prep_kernel(const float* __restrict__ X,
                            const float* __restrict__ theta,
                            const float* __restrict__ W) {
    if (blockIdx.x < PRE_BLOCKS) {
        const size_t idx = (size_t)blockIdx.x * blockDim.x + threadIdx.x; // half8 id
        const float4* X4  = (const float4*)X;
        const float4* Th4 = (const float4*)theta;
        const int k8 = (int)(idx & (K_TOT / 8 - 1));       // 0..127
        const int m  = (int)(idx >> 7);
        const float4 t0 = __ldg(Th4 + 2 * k8);
        const float4 t1 = __ldg(Th4 + 2 * k8 + 1);
        const float4 v0 = __ldg(X4 + 2 * idx);
        const float4 v1 = __ldg(X4 + 2 * idx + 1);
        __half h[8];
        h[0] = __float2half_rn(__cosf(v0.x + t0.x));
        h[1] = __float2half_rn(__cosf(v0.y + t0.y));
        h[2] = __float2half_rn(__cosf(v0.z + t0.z));
        h[3] = __float2half_rn(__cosf(v0.w + t0.w));
        h[4] = __float2half_rn(__cosf(v1.x + t1.x));
        h[5] = __float2half_rn(__cosf(v1.y + t1.y));
        h[6] = __float2half_rn(__cosf(v1.z + t1.z));
        h[7] = __float2half_rn(__cosf(v1.w + t1.w));
        // tiled + swizzled destination
        const int bm_blk = m >> 7;
        const int rowloc = m & 127;
        const int kt = k8 >> 3;
        const int cc = k8 & 7;
        const size_t dst = (size_t)bm_blk * ((size_t)NKT * TILE_BYTES)
                         + (size_t)kt * TILE_BYTES + tile_off(rowloc, cc);
        *(uint4*)((char*)g_Ah + dst) = *(const uint4*)h;
    } else {
        const int base = ((int)blockIdx.x - PRE_BLOCKS) * (256 * 8)
                       + (int)threadIdx.x * 8;
#pragma unroll
        for (int e = 0; e < 8; e++) {
            const int idx = base + e;          // 0 .. 1M-1
            const int n = idx >> 10;
            const int j = idx & 1023;
            const int q = j >> 8;
            const int hh = j & 255;
            const int k = (hh << 2) | q;
            const int bn_blk = n >> 7;
            const int rowloc = n & 127;
            const int kt = k >> 6;
            const int cc = (k >> 3) & 7;
            const size_t dst = (size_t)bn_blk * ((size_t)NKT * TILE_BYTES)
                             + (size_t)kt * TILE_BYTES + tile_off(rowloc, cc)
                             + (size_t)((k & 7) * 2);
            *(__half*)((char*)g_Wph + dst) = __float2half_rn(__ldg(W + idx));
        }
    }
}

// ---------------------------------------------------------------------------
// helpers
// ---------------------------------------------------------------------------
__device__ __forceinline__ uint32_t smem_u32(const void* p) {
    uint32_t a;
    asm("{ .reg .u64 t; cvta.to.shared.u64 t, %1; cvt.u32.u64 %0, t; }"
        : "=r"(a) : "l"(p));
    return a;
}

#define MBAR_INIT(addr, cnt) \
    asm volatile("mbarrier.init.shared.b64 [%0], %1;" :: "r"(addr), "r"(cnt) : "memory")

#define MBAR_EXPECT_TX(addr, bytes) \
    asm volatile("mbarrier.arrive.expect_tx.shared.b64 _, [%0], %1;" \
                 :: "r"(addr), "r"(bytes) : "memory")

#define MBAR_WAIT(addr, parity) do {                                              \
    asm volatile("{\n\t.reg .pred P1;\n\t"                                        \
        "LAB_W_%=:\n\t"                                                           \
        "mbarrier.try_wait.parity.acquire.cta.shared::cta.b64 P1, [%0], %1, 0x989680;\n\t" \
        "@P1 bra.uni LAB_D_%=;\n\t"                                               \
        "bra.uni LAB_W_%=;\n\t"                                                   \
        "LAB_D_%=:\n\t}"                                                          \
        :: "r"(addr), "r"(parity) : "memory");                                    \
} while (0)

#define BULK_CP(dst, src, bytes, mbar) \
    asm volatile("cp.async.bulk.shared::cluster.global.mbarrier::complete_tx::bytes " \
                 "[%0], [%1], %2, [%3];" \
                 :: "r"(dst), "l"(src), "r"(bytes), "r"(mbar) : "memory")

__device__ __forceinline__ void ldsm_x4(uint32_t* r, uint32_t addr) {
    asm volatile("ldmatrix.sync.aligned.m8n8.x4.shared.b16 {%0,%1,%2,%3}, [%4];"
                 : "=r"(r[0]), "=r"(r[1]), "=r"(r[2]), "=r"(r[3]) : "r"(addr));
}

__device__ __forceinline__ void mma_f16(float* c, const uint32_t* a,
                                        const uint32_t* b) {
    asm volatile(
        "mma.sync.aligned.m16n8k16.row.col.f32.f16.f16.f32 "
        "{%0,%1,%2,%3}, {%4,%5,%6,%7}, {%8,%9}, {%0,%1,%2,%3};\n"
        : "+f"(c[0]), "+f"(c[1]), "+f"(c[2]), "+f"(c[3])
        : "r"(a[0]), "r"(a[1]), "r"(a[2]), "r"(a[3]), "r"(b[0]), "r"(b[1]));
}

// ---------------------------------------------------------------------------
// Kernel 1: out = Ah @ Wph^T + bias
//   block 128x128, BK=64, 8 warps (2M x 4N), warp tile 64x32
//   3-stage cp.async.bulk (1 issuer thread) + mbarrier pipeline, 2 CTA/SM
// ---------------------------------------------------------------------------
__global__ void __launch_bounds__(256, 2)
qmha_gemm_kernel(const float* __restrict__ bias, float* __restrict__ out) {
    extern __shared__ char dsm[];
    __shared__ __align__(8) uint64_t full_bar_s[STAGES];

    const uint32_t base = (smem_u32(dsm) + 1023u) & ~1023u;
    const uint32_t full_bar = smem_u32(full_bar_s);

    const int tid  = threadIdx.x;
    const int warp = tid >> 5;
    const int lane = tid & 31;
    const int g    = lane >> 2;
    const int t    = lane & 3;
    const int wm   = (warp & 1) * 64;
    const int wn   = (warp >> 1) * 32;

    // block swizzle: N fastest -> co-resident blocks share A slab in L2
    const int bn_blk = blockIdx.x & 7;
    const int bm_blk = blockIdx.x >> 3;
    const int bn = bn_blk * BN;
    const int bm = bm_blk * BM;

    const char* aChunk = (const char*)g_Ah
                       + (size_t)bm_blk * ((size_t)NKT * TILE_BYTES);
    const char* bChunk = (const char*)g_Wph
                       + (size_t)bn_blk * ((size_t)NKT * TILE_BYTES);

    if (tid == 0) {
#pragma unroll
        for (int s = 0; s < STAGES; s++) MBAR_INIT(full_bar + 8 * s, 1);
    }
    __syncthreads();

    // issue one stage: 2 bulk copies -> full_bar[s], expect 32768 bytes
    auto ISSUE = [&](int s, int kt) {
        const uint32_t fb = full_bar + 8 * s;
        MBAR_EXPECT_TX(fb, STAGE_BYTES);
        BULK_CP(base + s * STAGE_BYTES, aChunk + (size_t)kt * TILE_BYTES,
                TILE_BYTES, fb);
        BULK_CP(base + s * STAGE_BYTES + TILE_BYTES,
                bChunk + (size_t)kt * TILE_BYTES, TILE_BYTES, fb);
    };

    if (tid == 0) { ISSUE(0, 0); ISSUE(1, 1); }

    // ldmatrix per-lane address components (same tile layout as before)
    const int rA  = lane & 15;
    const int aHi = lane >> 4;
    const uint32_t aRowB = (uint32_t)(wm + rA) * 128;
    const uint32_t aSw   = (uint32_t)(rA & 7);
    const int nLoc = (lane & 7) | ((lane >> 4) << 3);
    const int bHi  = (lane >> 3) & 1;
    const uint32_t bRowB = (uint32_t)(wn + nLoc) * 128;
    const uint32_t bSw   = (uint32_t)(nLoc & 7);

    float acc[4][4][4];
#pragma unroll
    for (int m = 0; m < 4; m++)
#pragma unroll
        for (int n = 0; n < 4; n++)
#pragma unroll
            for (int v = 0; v < 4; v++) acc[m][n][v] = 0.f;

    int stage = 0, parity = 0;
    for (int kt = 0; kt < NKT; kt++) {
        __syncthreads();                 // all done reading stage (kt+2)%3
        if (tid == 0 && kt + 2 < NKT) {
            const int s2 = stage + 2 >= STAGES ? stage + 2 - STAGES : stage + 2;
            ISSUE(s2, kt + 2);
        }
        MBAR_WAIT(full_bar + 8 * stage, parity);

        const uint32_t aS = base + stage * STAGE_BYTES + aRowB;
        const uint32_t bS = base + stage * STAGE_BYTES + TILE_BYTES + bRowB;
#pragma unroll
        for (int ks = 0; ks < 4; ks++) {               // 4 x k16 per BK=64
            const uint32_t ca = (uint32_t)((((2 * ks) | aHi) ^ aSw) << 4);
            const uint32_t cb = (uint32_t)((((2 * ks) | bHi) ^ bSw) << 4);
            uint32_t af[4][4], bf[2][4];
#pragma unroll
            for (int mt = 0; mt < 4; mt++)
                ldsm_x4(af[mt], aS + mt * 2048 + ca);
#pragma unroll
            for (int p = 0; p < 2; p++)
                ldsm_x4(bf[p], bS + p * 2048 + cb);
#pragma unroll
            for (int mt = 0; mt < 4; mt++)
#pragma unroll
                for (int nt = 0; nt < 4; nt++)
                    mma_f16(acc[mt][nt], af[mt], &bf[nt >> 1][(nt & 1) * 2]);
        }
        stage = stage + 1 >= STAGES ? 0 : stage + 1;
        if (stage == 0) parity ^= 1;
    }

    // epilogue: + bias, fp32 out
#pragma unroll
    for (int mt = 0; mt < 4; mt++) {
        const int m = bm + wm + mt * 16 + g;
#pragma unroll
        for (int nt = 0; nt < 4; nt++) {
            const int n = bn + wn + nt * 8 + 2 * t;
            const float b0 = __ldg(bias + n);
            const float b1 = __ldg(bias + n + 1);
            *(float2*)(out + (size_t)m * N_TOT + n) =
                make_float2(acc[mt][nt][0] + b0, acc[mt][nt][1] + b1);
            *(float2*)(out + (size_t)(m + 8) * N_TOT + n) =
                make_float2(acc[mt][nt][2] + b0, acc[mt][nt][3] + b1);
        }
    }
}

// ---------------------------------------------------------------------------
// launch
// ---------------------------------------------------------------------------
extern "C" void kernel_launch(void* const* d_in, const int* in_sizes, int n_in,
                              void* d_out, int out_size) {
    const float* x     = (const float*)d_in[0];   // (32768, 1, 1024)
    const float* theta = (const float*)d_in[1];   // (256, 4)
    const float* W     = (const float*)d_in[2];   // (1024, 1024)
    const float* b     = (const float*)d_in[3];   // (1024,)
    float* out = (float*)d_out;

    prep_kernel<<<PRE_BLOCKS + PERM_BLOCKS, 256>>>(x, theta, W);

    const int smem_bytes = STAGES * STAGE_BYTES + 1024;   // 97.25 KB
    cudaFuncSetAttribute(qmha_gemm_kernel,
                         cudaFuncAttributeMaxDynamicSharedMemorySize, smem_bytes);

    dim3 grid((M_TOT / BM) * (N_TOT / BN));       // 256 * 8 = 2048
    qmha_gemm_kernel<<<grid, 256, smem_bytes>>>(b, out);
}

// round 7
// speedup vs baseline: 3.6741x; 1.0762x over previous
#include <cuda_runtime.h>
#include <cuda_fp16.h>
#include <cstdint>

#define M_TOT 32768
#define N_TOT 1024
#define K_TOT 1024
#define BM 128
#define BN 128
#define BK 64
#define STAGES 3
#define TILE_BYTES 16384               // one 128x64 fp16 tile, swizzled
#define STAGE_BYTES (2 * TILE_BYTES)   // A tile + B tile
#define NKT (K_TOT / BK)               // 16
#define PRE_BLOCKS 16384               // A-precompute blocks
#define PERM_BLOCKS 512                // W-permute blocks

// scratch, both stored TILED + SWIZZLED:
//   g_Ah:  [bm_blk=256][kt=16][128x64 tile, 16KB, xor-swizzled]   (64 MB)
//   g_Wph: [bn_blk=8  ][kt=16][128x64 tile, 16KB, xor-swizzled]   ( 2 MB)
__device__ __half g_Ah[(size_t)M_TOT * K_TOT];
__device__ __half g_Wph[N_TOT * K_TOT];

// in-tile swizzled byte offset for (row 0..127, 16B-chunk cc 0..7)
__device__ __forceinline__ uint32_t tile_off(int row, int cc) {
    return (uint32_t)row * 128u + (uint32_t)((cc ^ (row & 7)) << 4);
}

// ---------------------------------------------------------------------------
// Kernel 0 (fused prep):
//  blocks [0, PRE_BLOCKS):            A = fp16(__cosf(x + theta)), tiled layout
//  blocks [PRE_BLOCKS, +PERM_BLOCKS): Wph[n, h*4+q] = fp16(W[n, q*256+h]), tiled
// ---------------------------------------------------------------------------
__global__ void prep_kernel(const float* __restrict__ X,
                            const float* __restrict__ theta,
                            const float* __restrict__ W) {
    if (blockIdx.x < PRE_BLOCKS) {
        const size_t idx = (size_t)blockIdx.x * blockDim.x + threadIdx.x; // half8 id
        const float4* X4  = (const float4*)X;
        const float4* Th4 = (const float4*)theta;
        const int k8 = (int)(idx & (K_TOT / 8 - 1));       // 0..127
        const int m  = (int)(idx >> 7);
        const float4 t0 = __ldg(Th4 + 2 * k8);
        const float4 t1 = __ldg(Th4 + 2 * k8 + 1);
        const float4 v0 = __ldg(X4 + 2 * idx);
        const float4 v1 = __ldg(X4 + 2 * idx + 1);
        __half h[8];
        h[0] = __float2half_rn(__cosf(v0.x + t0.x));
        h[1] = __float2half_rn(__cosf(v0.y + t0.y));
        h[2] = __float2half_rn(__cosf(v0.z + t0.z));
        h[3] = __float2half_rn(__cosf(v0.w + t0.w));
        h[4] = __float2half_rn(__cosf(v1.x + t1.x));
        h[5] = __float2half_rn(__cosf(v1.y + t1.y));
        h[6] = __float2half_rn(__cosf(v1.z + t1.z));
        h[7] = __float2half_rn(__cosf(v1.w + t1.w));
        const int bm_blk = m >> 7;
        const int rowloc = m & 127;
        const int kt = k8 >> 3;
        const int cc = k8 & 7;
        const size_t dst = (size_t)bm_blk * ((size_t)NKT * TILE_BYTES)
                         + (size_t)kt * TILE_BYTES + tile_off(rowloc, cc);
        *(uint4*)((char*)g_Ah + dst) = *(const uint4*)h;
    } else {
        const int base = ((int)blockIdx.x - PRE_BLOCKS) * (256 * 8)
                       + (int)threadIdx.x * 8;
#pragma unroll
        for (int e = 0; e < 8; e++) {
            const int idx = base + e;          // 0 .. 1M-1
            const int n = idx >> 10;
            const int j = idx & 1023;
            const int q = j >> 8;
            const int hh = j & 255;
            const int k = (hh << 2) | q;
            const int bn_blk = n >> 7;
            const int rowloc = n & 127;
            const int kt = k >> 6;
            const int cc = (k >> 3) & 7;
            const size_t dst = (size_t)bn_blk * ((size_t)NKT * TILE_BYTES)
                             + (size_t)kt * TILE_BYTES + tile_off(rowloc, cc)
                             + (size_t)((k & 7) * 2);
            *(__half*)((char*)g_Wph + dst) = __float2half_rn(__ldg(W + idx));
        }
    }
}

// ---------------------------------------------------------------------------
// helpers
// ---------------------------------------------------------------------------
__device__ __forceinline__ uint32_t smem_u32(const void* p) {
    uint32_t a;
    asm("{ .reg .u64 t; cvta.to.shared.u64 t, %1; cvt.u32.u64 %0, t; }"
        : "=r"(a) : "l"(p));
    return a;
}

#define MBAR_INIT(addr, cnt) \
    asm volatile("mbarrier.init.shared.b64 [%0], %1;" :: "r"(addr), "r"(cnt) : "memory")

#define MBAR_EXPECT_TX(addr, bytes) \
    asm volatile("mbarrier.arrive.expect_tx.shared.b64 _, [%0], %1;" \
                 :: "r"(addr), "r"(bytes) : "memory")

#define MBAR_ARRIVE(addr) \
    asm volatile("mbarrier.arrive.release.cta.shared.b64 _, [%0];" \
                 :: "r"(addr) : "memory")

#define MBAR_WAIT(addr, parity) do {                                              \
    asm volatile("{\n\t.reg .pred P1;\n\t"                                        \
        "LAB_W_%=:\n\t"                                                           \
        "mbarrier.try_wait.parity.acquire.cta.shared::cta.b64 P1, [%0], %1, 0x989680;\n\t" \
        "@P1 bra.uni LAB_D_%=;\n\t"                                               \
        "bra.uni LAB_W_%=;\n\t"                                                   \
        "LAB_D_%=:\n\t}"                                                          \
        :: "r"(addr), "r"(parity) : "memory");                                    \
} while (0)

#define BULK_CP(dst, src, bytes, mbar) \
    asm volatile("cp.async.bulk.shared::cluster.global.mbarrier::complete_tx::bytes " \
                 "[%0], [%1], %2, [%3];" \
                 :: "r"(dst), "l"(src), "r"(bytes), "r"(mbar) : "memory")

__device__ __forceinline__ void ldsm_x4(uint32_t* r, uint32_t addr) {
    asm volatile("ldmatrix.sync.aligned.m8n8.x4.shared.b16 {%0,%1,%2,%3}, [%4];"
                 : "=r"(r[0]), "=r"(r[1]), "=r"(r[2]), "=r"(r[3]) : "r"(addr));
}

__device__ __forceinline__ void mma_f16(float* c, const uint32_t* a,
                                        const uint32_t* b) {
    asm volatile(
        "mma.sync.aligned.m16n8k16.row.col.f32.f16.f16.f32 "
        "{%0,%1,%2,%3}, {%4,%5,%6,%7}, {%8,%9}, {%0,%1,%2,%3};\n"
        : "+f"(c[0]), "+f"(c[1]), "+f"(c[2]), "+f"(c[3])
        : "r"(a[0]), "r"(a[1]), "r"(a[2]), "r"(a[3]), "r"(b[0]), "r"(b[1]));
}

// ---------------------------------------------------------------------------
// Kernel 1: out = Ah @ Wph^T + bias
//   block 128x128, BK=64, 8 warps (2M x 4N), warp tile 64x32
//   3-stage cp.async.bulk pipeline with full+empty mbarriers (no __syncthreads
//   in the mainloop -> warps free-run up to one stage apart), 2 CTA/SM
// ---------------------------------------------------------------------------
__global__ void __launch_bounds__(256, 2)
qmha_gemm_kernel(const float* __restrict__ bias, float* __restrict__ out) {
    extern __shared__ char dsm[];
    __shared__ __align__(8) uint64_t bar_s[2 * STAGES];   // full[3], empty[3]

    const uint32_t base = (smem_u32(dsm) + 1023u) & ~1023u;
    const uint32_t full_bar  = smem_u32(bar_s);
    const uint32_t empty_bar = full_bar + 8 * STAGES;

    const int tid  = threadIdx.x;
    const int warp = tid >> 5;
    const int lane = tid & 31;
    const int g    = lane >> 2;
    const int t    = lane & 3;
    const int wm   = (warp & 1) * 64;
    const int wn   = (warp >> 1) * 32;

    // block swizzle: N fastest -> co-resident blocks share A slab in L2
    const int bn_blk = blockIdx.x & 7;
    const int bm_blk = blockIdx.x >> 3;
    const int bn = bn_blk * BN;
    const int bm = bm_blk * BM;

    const char* aChunk = (const char*)g_Ah
                       + (size_t)bm_blk * ((size_t)NKT * TILE_BYTES);
    const char* bChunk = (const char*)g_Wph
                       + (size_t)bn_blk * ((size_t)NKT * TILE_BYTES);

    if (tid == 0) {
#pragma unroll
        for (int s = 0; s < STAGES; s++) {
            MBAR_INIT(full_bar + 8 * s, 1);
            MBAR_INIT(empty_bar + 8 * s, 8);    // one arrive per warp
        }
    }
    __syncthreads();

    auto ISSUE = [&](int s, int kt) {
        const uint32_t fb = full_bar + 8 * s;
        MBAR_EXPECT_TX(fb, STAGE_BYTES);
        BULK_CP(base + s * STAGE_BYTES, aChunk + (size_t)kt * TILE_BYTES,
                TILE_BYTES, fb);
        BULK_CP(base + s * STAGE_BYTES + TILE_BYTES,
                bChunk + (size_t)kt * TILE_BYTES, TILE_BYTES, fb);
    };

    // issuer state: per-stage empty parity bits; stages 0,1 logically consumed
    // by the prologue issues (empty-wait skipped: guaranteed empty at start)
    uint32_t ep = 4;                    // {s0:0, s1:0, s2:1}
    if (tid == 0) { ISSUE(0, 0); ISSUE(1, 1); }

    // ldmatrix per-lane address components
    const int rA  = lane & 15;
    const int aHi = lane >> 4;
    const uint32_t aRowB = (uint32_t)(wm + rA) * 128;
    const uint32_t aSw   = (uint32_t)(rA & 7);
    const int nLoc = (lane & 7) | ((lane >> 4) << 3);
    const int bHi  = (lane >> 3) & 1;
    const uint32_t bRowB = (uint32_t)(wn + nLoc) * 128;
    const uint32_t bSw   = (uint32_t)(nLoc & 7);

    float acc[4][4][4];
#pragma unroll
    for (int m = 0; m < 4; m++)
#pragma unroll
        for (int n = 0; n < 4; n++)
#pragma unroll
            for (int v = 0; v < 4; v++) acc[m][n][v] = 0.f;

    int stage = 0, parity = 0;
    for (int kt = 0; kt < NKT; kt++) {
        // issuer: refill stage kt+2 once all 8 warps released it
        if (tid == 0 && kt + 2 < NKT) {
            const int s2 = stage + 2 >= STAGES ? stage + 2 - STAGES : stage + 2;
            MBAR_WAIT(empty_bar + 8 * s2, (ep >> s2) & 1);
            ep ^= 1u << s2;
            ISSUE(s2, kt + 2);
        }

        MBAR_WAIT(full_bar + 8 * stage, parity);

        const uint32_t aS = base + stage * STAGE_BYTES + aRowB;
        const uint32_t bS = base + stage * STAGE_BYTES + TILE_BYTES + bRowB;
#pragma unroll
        for (int ks = 0; ks < 4; ks++) {               // 4 x k16 per BK=64
            const uint32_t ca = (uint32_t)((((2 * ks) | aHi) ^ aSw) << 4);
            const uint32_t cb = (uint32_t)((((2 * ks) | bHi) ^ bSw) << 4);
            uint32_t af[4][4], bf[2][4];
#pragma unroll
            for (int mt = 0; mt < 4; mt++)
                ldsm_x4(af[mt], aS + mt * 2048 + ca);
#pragma unroll
            for (int p = 0; p < 2; p++)
                ldsm_x4(bf[p], bS + p * 2048 + cb);
#pragma unroll
            for (int mt = 0; mt < 4; mt++)
#pragma unroll
                for (int nt = 0; nt < 4; nt++)
                    mma_f16(acc[mt][nt], af[mt], &bf[nt >> 1][(nt & 1) * 2]);
        }

        // release this stage (MMA issue implies all LDSM smem reads done)
        if (lane == 0) MBAR_ARRIVE(empty_bar + 8 * stage);

        stage = stage + 1 >= STAGES ? 0 : stage + 1;
        if (stage == 0) parity ^= 1;
    }

    // epilogue: + bias, fp32 out
#pragma unroll
    for (int mt = 0; mt < 4; mt++) {
        const int m = bm + wm + mt * 16 + g;
#pragma unroll
        for (int nt = 0; nt < 4; nt++) {
            const int n = bn + wn + nt * 8 + 2 * t;
            const float b0 = __ldg(bias + n);
            const float b1 = __ldg(bias + n + 1);
            *(float2*)(out + (size_t)m * N_TOT + n) =
                make_float2(acc[mt][nt][0] + b0, acc[mt][nt][1] + b1);
            *(float2*)(out + (size_t)(m + 8) * N_TOT + n) =
                make_float2(acc[mt][nt][2] + b0, acc[mt][nt][3] + b1);
        }
    }
}

// ---------------------------------------------------------------------------
// launch
// ---------------------------------------------------------------------------
extern "C" void kernel_launch(void* const* d_in, const int* in_sizes, int n_in,
                              void* d_out, int out_size) {
    const float* x     = (const float*)d_in[0];   // (32768, 1, 1024)
    const float* theta = (const float*)d_in[1];   // (256, 4)
    const float* W     = (const float*)d_in[2];   // (1024, 1024)
    const float* b     = (const float*)d_in[3];   // (1024,)
    float* out = (float*)d_out;

    prep_kernel<<<PRE_BLOCKS + PERM_BLOCKS, 256>>>(x, theta, W);

    const int smem_bytes = STAGES * STAGE_BYTES + 1024;   // 97.25 KB
    cudaFuncSetAttribute(qmha_gemm_kernel,
                         cudaFuncAttributeMaxDynamicSharedMemorySize, smem_bytes);

    dim3 grid((M_TOT / BM) * (N_TOT / BN));       // 256 * 8 = 2048
    qmha_gemm_kernel<<<grid, 256, smem_bytes>>>(b, out);
}